// round 1
// baseline (speedup 1.0000x reference)
#include <cuda_runtime.h>
#include <math.h>

// ---------------- problem constants ----------------
#define IMG    256
#define CCH    192
#define NHEADS 6
#define DQK    32
#define DTOT   576      // 2*6*32 + 192
#define TOK    64       // 8x8 window
#define NWIN   4096     // 4 * 32 * 32

// ---------------- smem layout (floats) ----------------
#define XST_LD 68       // XsT[192][68]  (transposed x window, float4-aligned rows)
#define QKV_LD 34       // per-head Q/K/V rows [64][34] (float2-aligned)
#define S_LD   68       // softmax probs [64][68]
#define AO_LD  196      // attention out [64][196]
#define WS_LD  194      // weight staging [16][194]

#define OFF_XST 0
#define SZ_XST  (192*XST_LD)        // 13056
#define OFF_WS  (OFF_XST + SZ_XST)
#define SZ_WS   (16*WS_LD)          // 3104
#define OFF_QKV (OFF_WS + SZ_WS)
#define SZ_QKV  (2*3*64*QKV_LD)     // 13056
#define OFF_S   (OFF_QKV + SZ_QKV)
#define SZ_S    (2*64*S_LD)         // 8704
#define OFF_AO  (OFF_S + SZ_S)
#define SZ_AO   (64*AO_LD)          // 12544
#define SMEM_FLOATS (OFF_AO + SZ_AO)            // 50464
#define SMEM_BYTES  (SMEM_FLOATS * 4)           // 201856

// relative-position bias table rb[head][q][k]
__device__ float g_rb[NHEADS * TOK * TOK];

// ---------------- kernel 1: CPB MLP + gather ----------------
__global__ void cpb_kernel(const float* __restrict__ w1, const float* __restrict__ b1,
                           const float* __restrict__ w2) {
    __shared__ float tab16[225][6];
    int t = threadIdx.x;
    if (t < 225) {
        float ci = (float)(t / 15 - 7) * (8.0f / 7.0f);
        float cj = (float)(t % 15 - 7) * (8.0f / 7.0f);
        const float inv_log8 = 1.0f / logf(8.0f);
        float tx = copysignf(log1pf(fabsf(ci)) * inv_log8, ci);
        float ty = copysignf(log1pf(fabsf(cj)) * inv_log8, cj);
        float o[6] = {0.f, 0.f, 0.f, 0.f, 0.f, 0.f};
        for (int k = 0; k < 512; k++) {
            float h = fmaxf(tx * w1[k] + ty * w1[512 + k] + b1[k], 0.0f);
            #pragma unroll
            for (int hh = 0; hh < 6; hh++) o[hh] += h * w2[k * 6 + hh];
        }
        #pragma unroll
        for (int hh = 0; hh < 6; hh++) tab16[t][hh] = 16.0f / (1.0f + expf(-o[hh]));
    }
    __syncthreads();
    for (int idx = t; idx < NHEADS * TOK * TOK; idx += blockDim.x) {
        int h = idx >> 12;           // / 4096
        int r = idx & 4095;
        int p = r >> 6;              // query token
        int q = r & 63;              // key token
        int ri = (p >> 3) - (q >> 3) + 7;
        int rj = (p & 7) - (q & 7) + 7;
        g_rb[idx] = tab16[ri * 15 + rj][h];
    }
}

// ---------------- kernel 2: fused window attention ----------------
__global__ __launch_bounds__(512, 1)
void swin_kernel(const float* __restrict__ x, const float* __restrict__ qkv_w,
                 const float* __restrict__ q_bias, const float* __restrict__ v_bias,
                 const float* __restrict__ scale,
                 const float* __restrict__ proj_w, const float* __restrict__ proj_b,
                 float* __restrict__ out) {
    extern __shared__ float sm[];
    float* XST = sm + OFF_XST;
    float* WS  = sm + OFF_WS;
    float* QKV = sm + OFF_QKV;
    float* S   = sm + OFF_S;
    float* AO  = sm + OFF_AO;

    const int t   = threadIdx.x;
    const int win = blockIdx.x;
    const int b   = win >> 10;
    const int wy  = (win >> 5) & 31;
    const int wx  = win & 31;

    // ---- Phase 0: load x window transposed: XST[c][r] ----
    for (int idx = t; idx < TOK * CCH; idx += 512) {
        int r = idx / CCH;
        int c = idx - r * CCH;
        int yy = (wy << 3) + (r >> 3);
        int xx = (wx << 3) + (r & 7);
        XST[c * XST_LD + r] = x[(((b << 8) + yy) * IMG + xx) * CCH + c];
    }

    const int sub = t >> 8;        // which head of the pair
    const int ts  = t & 255;
    const int ty  = ts >> 4;       // 0..15 row group (4 rows)
    const int tx  = ts & 15;       // 0..15 col group (6 cols)

    // ---- head pairs ----
    for (int hp = 0; hp < 3; hp++) {
        const int h = hp * 2 + sub;

        // ---- qkv GEMM: out[64][96] for head h, K = 192 ----
        float acc[4][6];
        #pragma unroll
        for (int i = 0; i < 4; i++)
            #pragma unroll
            for (int j = 0; j < 6; j++) acc[i][j] = 0.f;

        for (int k0 = 0; k0 < CCH; k0 += 16) {
            __syncthreads();   // also orders phase-0 XST writes / prev-pair PV reads
            for (int idx = t; idx < 16 * 192; idx += 512) {
                int kk = idx / 192, d = idx - kk * 192;
                WS[kk * WS_LD + d] = qkv_w[(k0 + kk) * DTOT + hp * 192 + d];
            }
            __syncthreads();
            #pragma unroll
            for (int kk = 0; kk < 16; kk++) {
                int c = k0 + kk;
                float4 a4 = *reinterpret_cast<const float4*>(&XST[c * XST_LD + (ty << 2)]);
                float a[4] = {a4.x, a4.y, a4.z, a4.w};
                const float* wrow = &WS[kk * WS_LD + sub * 96 + tx * 6];
                float2 b01 = *reinterpret_cast<const float2*>(wrow);
                float2 b23 = *reinterpret_cast<const float2*>(wrow + 2);
                float2 b45 = *reinterpret_cast<const float2*>(wrow + 4);
                float bb[6] = {b01.x, b01.y, b23.x, b23.y, b45.x, b45.y};
                #pragma unroll
                for (int i = 0; i < 4; i++)
                    #pragma unroll
                    for (int j = 0; j < 6; j++)
                        acc[i][j] = fmaf(a[i], bb[j], acc[i][j]);
            }
        }
        // store q/k/v with bias (reference bias layout: d<192 -> q_bias, <384 -> 0, else v_bias)
        #pragma unroll
        for (int j = 0; j < 6; j++) {
            int col   = tx * 6 + j;
            int dglob = h * 96 + col;
            float bias = (dglob < 192) ? q_bias[dglob]
                       : ((dglob < 384) ? 0.0f : v_bias[dglob - 384]);
            int part = col >> 5;   // 0=q 1=k 2=v
            int d    = col & 31;
            #pragma unroll
            for (int i = 0; i < 4; i++) {
                int row = (ty << 2) + i;
                QKV[((sub * 3 + part) * 64 + row) * QKV_LD + d] = acc[i][j] + bias;
            }
        }
        __syncthreads();

        // ---- L2 normalize q (with logit scale) and k ----
        if (t < 256) {
            int sn    = t >> 7;        // head-of-pair
            int which = (t >> 6) & 1;  // 0=q 1=k
            int row   = t & 63;
            float* rp = &QKV[((sn * 3 + which) * 64 + row) * QKV_LD];
            float ss = 0.f;
            #pragma unroll
            for (int d = 0; d < 32; d++) ss = fmaf(rp[d], rp[d], ss);
            float inv = rsqrtf(fmaxf(ss, 1.55e-05f));
            if (which == 0) {
                float sc = scale[hp * 2 + sn];
                inv *= expf(fminf(sc, 4.605170185988092f));   // ln(100)
            }
            #pragma unroll
            for (int d = 0; d < 32; d++) rp[d] *= inv;
        }
        __syncthreads();

        // ---- scores + bias + softmax (4 threads per query row) ----
        {
            int i  = ts >> 2;
            int jg = ts & 3;
            const float* qp = &QKV[((sub * 3 + 0) * 64 + i) * QKV_LD];
            float q[32];
            #pragma unroll
            for (int d = 0; d < 32; d += 2) {
                float2 v2 = *reinterpret_cast<const float2*>(qp + d);
                q[d] = v2.x; q[d + 1] = v2.y;
            }
            float p[16];
            float m = -1e30f;
            const float* rbp = &g_rb[h * 4096 + i * 64 + jg * 16];
            #pragma unroll
            for (int jj = 0; jj < 16; jj++) {
                int j = jg * 16 + jj;
                const float* kp = &QKV[((sub * 3 + 1) * 64 + j) * QKV_LD];
                float dot = 0.f;
                #pragma unroll
                for (int d = 0; d < 32; d += 2) {
                    float2 v2 = *reinterpret_cast<const float2*>(kp + d);
                    dot = fmaf(q[d],     v2.x, dot);
                    dot = fmaf(q[d + 1], v2.y, dot);
                }
                dot += rbp[jj];
                p[jj] = dot;
                m = fmaxf(m, dot);
            }
            m = fmaxf(m, __shfl_xor_sync(0xffffffffu, m, 1));
            m = fmaxf(m, __shfl_xor_sync(0xffffffffu, m, 2));
            float sum = 0.f;
            #pragma unroll
            for (int jj = 0; jj < 16; jj++) { p[jj] = __expf(p[jj] - m); sum += p[jj]; }
            sum += __shfl_xor_sync(0xffffffffu, sum, 1);
            sum += __shfl_xor_sync(0xffffffffu, sum, 2);
            float rinv = 1.0f / sum;
            #pragma unroll
            for (int jj = 0; jj < 16; jj++)
                S[(sub * 64 + i) * S_LD + jg * 16 + jj] = p[jj] * rinv;
        }
        __syncthreads();

        // ---- PV: 4 threads per query row, 8 v-channels each ----
        {
            int i  = ts >> 2;
            int dg = ts & 3;
            float o[8] = {0.f, 0.f, 0.f, 0.f, 0.f, 0.f, 0.f, 0.f};
            const float* srow = &S[(sub * 64 + i) * S_LD];
            #pragma unroll 4
            for (int j = 0; j < 64; j++) {
                float pv = srow[j];
                const float* vp = &QKV[((sub * 3 + 2) * 64 + j) * QKV_LD + dg * 8];
                #pragma unroll
                for (int d = 0; d < 8; d += 2) {
                    float2 v2 = *reinterpret_cast<const float2*>(vp + d);
                    o[d]     = fmaf(pv, v2.x, o[d]);
                    o[d + 1] = fmaf(pv, v2.y, o[d + 1]);
                }
            }
            #pragma unroll
            for (int d = 0; d < 8; d++)
                AO[i * AO_LD + h * 32 + dg * 8 + d] = o[d];
        }
        // next pair's first __syncthreads orders QKV/S reuse
    }

    // ---- output projection: Y[64][192] = AO @ proj_w + proj_b ----
    {
        const int ty2 = t >> 5;   // 0..15 (4 rows)
        const int tx2 = t & 31;   // 0..31 (6 cols)
        float acc[4][6];
        #pragma unroll
        for (int i = 0; i < 4; i++)
            #pragma unroll
            for (int j = 0; j < 6; j++) acc[i][j] = 0.f;

        for (int k0 = 0; k0 < CCH; k0 += 16) {
            __syncthreads();   // first iter also orders PV AO writes
            for (int idx = t; idx < 16 * 192; idx += 512) {
                int kk = idx / 192, d = idx - kk * 192;
                WS[kk * WS_LD + d] = proj_w[(k0 + kk) * CCH + d];
            }
            __syncthreads();
            #pragma unroll
            for (int kk = 0; kk < 16; kk++) {
                int c = k0 + kk;
                float a[4];
                #pragma unroll
                for (int i = 0; i < 4; i++) a[i] = AO[((ty2 << 2) + i) * AO_LD + c];
                const float* wrow = &WS[kk * WS_LD + tx2 * 6];
                float2 b01 = *reinterpret_cast<const float2*>(wrow);
                float2 b23 = *reinterpret_cast<const float2*>(wrow + 2);
                float2 b45 = *reinterpret_cast<const float2*>(wrow + 4);
                float bb[6] = {b01.x, b01.y, b23.x, b23.y, b45.x, b45.y};
                #pragma unroll
                for (int i = 0; i < 4; i++)
                    #pragma unroll
                    for (int j = 0; j < 6; j++)
                        acc[i][j] = fmaf(a[i], bb[j], acc[i][j]);
            }
        }
        #pragma unroll
        for (int i = 0; i < 4; i++) {
            int row = (ty2 << 2) + i;
            int yy = (wy << 3) + (row >> 3);
            int xx = (wx << 3) + (row & 7);
            float* op = &out[(((b << 8) + yy) * IMG + xx) * CCH + tx2 * 6];
            #pragma unroll
            for (int j = 0; j < 6; j++) op[j] = acc[i][j] + proj_b[tx2 * 6 + j];
        }
    }
}

// ---------------- launch ----------------
extern "C" void kernel_launch(void* const* d_in, const int* in_sizes, int n_in,
                              void* d_out, int out_size) {
    (void)in_sizes; (void)n_in; (void)out_size;
    const float* x      = (const float*)d_in[0];
    const float* qkv_w  = (const float*)d_in[1];
    const float* q_bias = (const float*)d_in[2];
    const float* v_bias = (const float*)d_in[3];
    const float* scale  = (const float*)d_in[4];
    const float* cpb_w1 = (const float*)d_in[5];
    const float* cpb_b1 = (const float*)d_in[6];
    const float* cpb_w2 = (const float*)d_in[7];
    const float* proj_w = (const float*)d_in[8];
    const float* proj_b = (const float*)d_in[9];
    float* out = (float*)d_out;

    cudaFuncSetAttribute(swin_kernel, cudaFuncAttributeMaxDynamicSharedMemorySize, SMEM_BYTES);

    cpb_kernel<<<1, 256>>>(cpb_w1, cpb_b1, cpb_w2);
    swin_kernel<<<NWIN, 512, SMEM_BYTES>>>(x, qkv_w, q_bias, v_bias, scale,
                                           proj_w, proj_b, out);
}

// round 3
// speedup vs baseline: 1.7794x; 1.7794x over previous
#include <cuda_runtime.h>
#include <cuda_bf16.h>
#include <math.h>
#include <stdint.h>

// ================= problem constants =================
#define IMG    256
#define CCH    192      // channels (= K of both GEMMs)
#define NHEADS 6
#define DTOT   576      // fused qkv dim
#define TOK    64
#define NWIN   4096
#define NTOK   262144   // 4*256*256 tokens

// ================= device scratch =================
__device__ float g_qkv[(size_t)NTOK * DTOT];            // 604 MB
__device__ float g_ao [(size_t)NTOK * CCH];             // 201 MB
__device__ uint32_t g_wq_frag[72 * 24 * 64];            // qkv weight frags [nt][step][lane][2]
__device__ uint32_t g_wp_frag[24 * 24 * 64];            // proj weight frags
__device__ float g_bq[DTOT];                            // fused qkv bias
__device__ float g_rb[NHEADS * TOK * TOK];              // relative position bias

// ================= asm helpers (baseline sm_103 PTX only) =================
__device__ __forceinline__ uint32_t smem_u32(const void* p) {
    uint32_t a;
    asm("{ .reg .u64 t; cvta.to.shared.u64 t, %1; cvt.u32.u64 %0, t; }" : "=r"(a) : "l"(p));
    return a;
}
__device__ __forceinline__ void ldsm4(uint32_t* r, uint32_t addr) {
    asm volatile("ldmatrix.sync.aligned.m8n8.x4.shared.b16 {%0,%1,%2,%3}, [%4];"
                 : "=r"(r[0]), "=r"(r[1]), "=r"(r[2]), "=r"(r[3]) : "r"(addr));
}
__device__ __forceinline__ void lds64(uint32_t* r, uint32_t addr) {
    asm volatile("ld.shared.v2.u32 {%0,%1}, [%2];" : "=r"(r[0]), "=r"(r[1]) : "r"(addr));
}
__device__ __forceinline__ void mma16816(float* d, const uint32_t* a, const uint32_t* b) {
    asm volatile("mma.sync.aligned.m16n8k16.row.col.f32.bf16.bf16.f32 "
                 "{%0,%1,%2,%3}, {%4,%5,%6,%7}, {%8,%9}, {%0,%1,%2,%3};"
                 : "+f"(d[0]), "+f"(d[1]), "+f"(d[2]), "+f"(d[3])
                 : "r"(a[0]), "r"(a[1]), "r"(a[2]), "r"(a[3]), "r"(b[0]), "r"(b[1]));
}
__device__ __forceinline__ void cpasync16(uint32_t saddr, const void* g) {
    asm volatile("cp.async.cg.shared.global [%0], [%1], 16;" :: "r"(saddr), "l"(g) : "memory");
}
#define CP_COMMIT() asm volatile("cp.async.commit_group;" ::: "memory")
#define CP_WAIT0()  asm volatile("cp.async.wait_group 0;" ::: "memory")
#define CP_WAIT1()  asm volatile("cp.async.wait_group 1;" ::: "memory")

__device__ __forceinline__ uint16_t bf_hi(float v) {
    return __bfloat16_as_ushort(__float2bfloat16(v));
}
__device__ __forceinline__ uint16_t bf_lo(float v) {
    __nv_bfloat16 h = __float2bfloat16(v);
    return __bfloat16_as_ushort(__float2bfloat16(v - __bfloat162float(h)));
}

// ================= kernel: weight prep (fragment pack) =================
// Frag tables: [ntile][step][lane][2] u32; steps 0..11 = hi(k16 block t), 12..23 = lo.
// B[k][n] fragment: reg r, lane l -> k_local = 2*(l&3)+8r (+1 in hi16), n_local = l>>2.
__global__ void prep_kernel(const float* __restrict__ qkv_w, const float* __restrict__ proj_w,
                            const float* __restrict__ q_bias, const float* __restrict__ v_bias) {
    int gtid = blockIdx.x * blockDim.x + threadIdx.x;
    int nth = gridDim.x * blockDim.x;
    for (int idx = gtid; idx < 72 * 24 * 64; idx += nth) {
        int r = idx & 1, l = (idx >> 1) & 31;
        int st = (idx >> 6) % 24, nt = (idx >> 6) / 24;
        int ko = 16 * (st % 12) + 2 * (l & 3) + 8 * r;
        int n = nt * 8 + (l >> 2);
        float v0 = qkv_w[ko * DTOT + n];
        float v1 = qkv_w[(ko + 1) * DTOT + n];
        uint32_t p0 = (st < 12) ? bf_hi(v0) : bf_lo(v0);
        uint32_t p1 = (st < 12) ? bf_hi(v1) : bf_lo(v1);
        g_wq_frag[idx] = p0 | (p1 << 16);
    }
    for (int idx = gtid; idx < 24 * 24 * 64; idx += nth) {
        int r = idx & 1, l = (idx >> 1) & 31;
        int st = (idx >> 6) % 24, nt = (idx >> 6) / 24;
        int ko = 16 * (st % 12) + 2 * (l & 3) + 8 * r;
        int n = nt * 8 + (l >> 2);
        float v0 = proj_w[ko * CCH + n];
        float v1 = proj_w[(ko + 1) * CCH + n];
        uint32_t p0 = (st < 12) ? bf_hi(v0) : bf_lo(v0);
        uint32_t p1 = (st < 12) ? bf_hi(v1) : bf_lo(v1);
        g_wp_frag[idx] = p0 | (p1 << 16);
    }
    for (int n = gtid; n < DTOT; n += nth)
        g_bq[n] = (n < 192) ? q_bias[n] : ((n < 384) ? 0.0f : v_bias[n - 384]);
}

// ================= kernel: CPB MLP + gather =================
__global__ void cpb_kernel(const float* __restrict__ w1, const float* __restrict__ b1,
                           const float* __restrict__ w2) {
    __shared__ float tab16[225][6];
    int t = threadIdx.x;
    if (t < 225) {
        float ci = (float)(t / 15 - 7) * (8.0f / 7.0f);
        float cj = (float)(t % 15 - 7) * (8.0f / 7.0f);
        const float inv_log8 = 1.0f / logf(8.0f);
        float tx = copysignf(log1pf(fabsf(ci)) * inv_log8, ci);
        float ty = copysignf(log1pf(fabsf(cj)) * inv_log8, cj);
        float o[6] = {0.f, 0.f, 0.f, 0.f, 0.f, 0.f};
        for (int k = 0; k < 512; k++) {
            float h = fmaxf(tx * w1[k] + ty * w1[512 + k] + b1[k], 0.0f);
            #pragma unroll
            for (int hh = 0; hh < 6; hh++) o[hh] += h * w2[k * 6 + hh];
        }
        #pragma unroll
        for (int hh = 0; hh < 6; hh++) tab16[t][hh] = 16.0f / (1.0f + expf(-o[hh]));
    }
    __syncthreads();
    for (int idx = t; idx < NHEADS * TOK * TOK; idx += blockDim.x) {
        int h = idx >> 12;
        int r = idx & 4095;
        int p = r >> 6, q = r & 63;
        int ri = (p >> 3) - (q >> 3) + 7;
        int rj = (p & 7) - (q & 7) + 7;
        g_rb[idx] = tab16[ri * 15 + rj][h];
    }
}

// ================= GEMM: D[128 x Ntot] = src[128 x 192] @ W + bias =================
// bf16 3-term hi/lo split via mma.sync m16n8k16.
// smem: A [128 rows][392 bf16] (hi cols 0..191, lo 192..383, pad 8)  = 100352 B
//       B double buffer: 2 x [8 nt][24 step][32 lane][2 u32]         = 2 x 49152 B
#define A_ROW_B   784
#define OFF_A     0
#define OFF_B0    100352
#define OFF_B1    149504
#define GEMM_SMEM 198656
#define B_CHUNK_U32 12288   // 8*24*64

__global__ __launch_bounds__(256, 1)
void gemm_kernel(const float* __restrict__ src_arg, float* __restrict__ dst_arg,
                 const float* __restrict__ bias_arg, int mode) {
    extern __shared__ char smc[];
    const uint32_t smb = smem_u32(smc);

    const float* src = (mode == 0) ? src_arg : g_ao;
    float* dst       = (mode == 0) ? g_qkv   : dst_arg;
    const float* bias = (mode == 0) ? g_bq    : bias_arg;
    const uint32_t* wfrag = (mode == 0) ? g_wq_frag : g_wp_frag;
    const int Ntot = (mode == 0) ? DTOT : CCH;
    const int nch = Ntot / 64;

    const int tid = threadIdx.x;
    const int m0 = blockIdx.x * 128;
    const int w = tid >> 5, lane = tid & 31;
    const int wm = w >> 1, wn = w & 1;

    // ---- build A hi/lo in smem ----
    for (int idx = tid; idx < 128 * 48; idx += 256) {
        int r = idx / 48, k4 = idx - r * 48;
        int k = k4 * 4;
        float4 v = *reinterpret_cast<const float4*>(&src[(size_t)(m0 + r) * CCH + k]);
        uint32_t h01 = (uint32_t)bf_hi(v.x) | ((uint32_t)bf_hi(v.y) << 16);
        uint32_t h23 = (uint32_t)bf_hi(v.z) | ((uint32_t)bf_hi(v.w) << 16);
        uint32_t l01 = (uint32_t)bf_lo(v.x) | ((uint32_t)bf_lo(v.y) << 16);
        uint32_t l23 = (uint32_t)bf_lo(v.z) | ((uint32_t)bf_lo(v.w) << 16);
        char* rowp = smc + OFF_A + r * A_ROW_B;
        *reinterpret_cast<uint2*>(rowp + 2 * k)       = make_uint2(h01, h23);
        *reinterpret_cast<uint2*>(rowp + 384 + 2 * k) = make_uint2(l01, l23);
    }

    // ---- prefetch B chunk 0 ----
    {
        const char* gb = (const char*)(wfrag);
        #pragma unroll
        for (int i = 0; i < 12; i++) {
            int off = (tid + i * 256) * 16;
            cpasync16(smb + OFF_B0 + off, gb + off);
        }
        CP_COMMIT();
    }

    const uint32_t a_base = smb + OFF_A + (wm * 32 + (lane & 15)) * A_ROW_B + (lane >> 4) * 16;

    for (int c = 0; c < nch; c++) {
        if (c + 1 < nch) {
            const char* gb = (const char*)(wfrag + (size_t)(c + 1) * B_CHUNK_U32);
            uint32_t bb = smb + (((c + 1) & 1) ? OFF_B1 : OFF_B0);
            #pragma unroll
            for (int i = 0; i < 12; i++) {
                int off = (tid + i * 256) * 16;
                cpasync16(bb + off, gb + off);
            }
            CP_COMMIT();
            CP_WAIT1();
        } else {
            CP_WAIT0();
        }
        __syncthreads();

        const uint32_t b_base = smb + ((c & 1) ? OFF_B1 : OFF_B0);

        float acc[2][4][4];
        #pragma unroll
        for (int i = 0; i < 2; i++)
            #pragma unroll
            for (int j = 0; j < 4; j++)
                #pragma unroll
                for (int e = 0; e < 4; e++) acc[i][j][e] = 0.f;

        #pragma unroll 4
        for (int t = 0; t < 12; t++) {
            uint32_t ah[2][4], al[2][4], bh[4][2], bl[4][2];
            #pragma unroll
            for (int mf = 0; mf < 2; mf++) {
                uint32_t aaddr = a_base + mf * 16 * A_ROW_B + t * 32;
                ldsm4(ah[mf], aaddr);
                ldsm4(al[mf], aaddr + 384);
            }
            #pragma unroll
            for (int nf = 0; nf < 4; nf++) {
                int nt = wn * 4 + nf;
                uint32_t baddr = b_base + (((nt * 24 + t) * 32 + lane) << 3);
                lds64(bh[nf], baddr);
                lds64(bl[nf], baddr + 3072);   // step +12 (lo)
            }
            #pragma unroll
            for (int mf = 0; mf < 2; mf++)
                #pragma unroll
                for (int nf = 0; nf < 4; nf++) {
                    mma16816(acc[mf][nf], ah[mf], bh[nf]);
                    mma16816(acc[mf][nf], al[mf], bh[nf]);
                    mma16816(acc[mf][nf], ah[mf], bl[nf]);
                }
        }

        // ---- epilogue: direct global stores with bias ----
        #pragma unroll
        for (int mf = 0; mf < 2; mf++) {
            int row = m0 + wm * 32 + mf * 16 + (lane >> 2);
            #pragma unroll
            for (int nf = 0; nf < 4; nf++) {
                int colg = c * 64 + wn * 32 + nf * 8 + 2 * (lane & 3);
                float2 bv = *reinterpret_cast<const float2*>(&bias[colg]);
                float2 v0 = make_float2(acc[mf][nf][0] + bv.x, acc[mf][nf][1] + bv.y);
                float2 v1 = make_float2(acc[mf][nf][2] + bv.x, acc[mf][nf][3] + bv.y);
                *reinterpret_cast<float2*>(&dst[(size_t)row * Ntot + colg]) = v0;
                *reinterpret_cast<float2*>(&dst[(size_t)(row + 8) * Ntot + colg]) = v1;
            }
        }
        __syncthreads();
    }
}

// ================= kernel: per-window fp32 attention =================
#define QKV_LD 34
#define S_LD   68
#define ATTN_SMEM ((2*3*64*QKV_LD + 2*64*S_LD) * 4)

__global__ __launch_bounds__(512, 2)
void attn_kernel(const float* __restrict__ scale) {
    extern __shared__ float sm[];
    float* QKV = sm;
    float* S   = sm + 2 * 3 * 64 * QKV_LD;

    const int t   = threadIdx.x;
    const int win = blockIdx.x;
    const int b   = win >> 10;
    const int wy  = (win >> 5) & 31;
    const int wx  = win & 31;
    const int sub = t >> 8;
    const int ts  = t & 255;

    for (int hp = 0; hp < 3; hp++) {
        __syncthreads();
        for (int idx = t; idx < 64 * 192; idx += 512) {
            int r = idx / 192, c = idx - r * 192;
            int y = (wy << 3) + (r >> 3), x = (wx << 3) + (r & 7);
            size_t tok = (size_t)(((b << 8) + y) * IMG + x);
            int sh = c / 96;
            int rem = c - sh * 96;
            int part = rem >> 5, d = rem & 31;
            QKV[((sh * 3 + part) * 64 + r) * QKV_LD + d] = g_qkv[tok * DTOT + hp * 192 + c];
        }
        __syncthreads();

        if (t < 256) {
            int sn = t >> 7, which = (t >> 6) & 1, row = t & 63;
            float* rp = &QKV[((sn * 3 + which) * 64 + row) * QKV_LD];
            float ss = 0.f;
            #pragma unroll
            for (int d = 0; d < 32; d++) ss = fmaf(rp[d], rp[d], ss);
            float inv = rsqrtf(fmaxf(ss, 1.55e-05f));
            if (which == 0) {
                float sc = scale[hp * 2 + sn];
                inv *= expf(fminf(sc, 4.605170185988092f));
            }
            #pragma unroll
            for (int d = 0; d < 32; d++) rp[d] *= inv;
        }
        __syncthreads();

        const int h = hp * 2 + sub;
        {
            int i = ts >> 2, jg = ts & 3;
            const float* qp = &QKV[((sub * 3 + 0) * 64 + i) * QKV_LD];
            float q[32];
            #pragma unroll
            for (int d = 0; d < 32; d += 2) {
                float2 v2 = *reinterpret_cast<const float2*>(qp + d);
                q[d] = v2.x; q[d + 1] = v2.y;
            }
            float p[16];
            float m = -1e30f;
            const float* rbp = &g_rb[h * 4096 + i * 64 + jg * 16];
            #pragma unroll
            for (int jj = 0; jj < 16; jj++) {
                int j = jg * 16 + jj;
                const float* kp = &QKV[((sub * 3 + 1) * 64 + j) * QKV_LD];
                float dot = 0.f;
                #pragma unroll
                for (int d = 0; d < 32; d += 2) {
                    float2 v2 = *reinterpret_cast<const float2*>(kp + d);
                    dot = fmaf(q[d], v2.x, dot);
                    dot = fmaf(q[d + 1], v2.y, dot);
                }
                dot += rbp[jj];
                p[jj] = dot;
                m = fmaxf(m, dot);
            }
            m = fmaxf(m, __shfl_xor_sync(0xffffffffu, m, 1));
            m = fmaxf(m, __shfl_xor_sync(0xffffffffu, m, 2));
            float sum = 0.f;
            #pragma unroll
            for (int jj = 0; jj < 16; jj++) { p[jj] = __expf(p[jj] - m); sum += p[jj]; }
            sum += __shfl_xor_sync(0xffffffffu, sum, 1);
            sum += __shfl_xor_sync(0xffffffffu, sum, 2);
            float rinv = 1.0f / sum;
            #pragma unroll
            for (int jj = 0; jj < 16; jj++)
                S[(sub * 64 + i) * S_LD + jg * 16 + jj] = p[jj] * rinv;
        }
        __syncthreads();

        {
            int i = ts >> 2, dg = ts & 3;
            float o[8] = {0.f, 0.f, 0.f, 0.f, 0.f, 0.f, 0.f, 0.f};
            const float* srow = &S[(sub * 64 + i) * S_LD];
            #pragma unroll 4
            for (int j = 0; j < 64; j++) {
                float pv = srow[j];
                const float* vp = &QKV[((sub * 3 + 2) * 64 + j) * QKV_LD + dg * 8];
                #pragma unroll
                for (int d = 0; d < 8; d += 2) {
                    float2 v2 = *reinterpret_cast<const float2*>(vp + d);
                    o[d]     = fmaf(pv, v2.x, o[d]);
                    o[d + 1] = fmaf(pv, v2.y, o[d + 1]);
                }
            }
            int y = (wy << 3) + (i >> 3), x = (wx << 3) + (i & 7);
            size_t tok = (size_t)(((b << 8) + y) * IMG + x);
            float* op = &g_ao[tok * CCH + h * 32 + dg * 8];
            #pragma unroll
            for (int d = 0; d < 8; d++) op[d] = o[d];
        }
    }
}

// ================= launch =================
extern "C" void kernel_launch(void* const* d_in, const int* in_sizes, int n_in,
                              void* d_out, int out_size) {
    (void)in_sizes; (void)n_in; (void)out_size;
    const float* x      = (const float*)d_in[0];
    const float* qkv_w  = (const float*)d_in[1];
    const float* q_bias = (const float*)d_in[2];
    const float* v_bias = (const float*)d_in[3];
    const float* scale  = (const float*)d_in[4];
    const float* cpb_w1 = (const float*)d_in[5];
    const float* cpb_b1 = (const float*)d_in[6];
    const float* cpb_w2 = (const float*)d_in[7];
    const float* proj_w = (const float*)d_in[8];
    const float* proj_b = (const float*)d_in[9];
    float* out = (float*)d_out;

    cudaFuncSetAttribute(gemm_kernel, cudaFuncAttributeMaxDynamicSharedMemorySize, GEMM_SMEM);
    cudaFuncSetAttribute(attn_kernel, cudaFuncAttributeMaxDynamicSharedMemorySize, ATTN_SMEM);

    prep_kernel<<<64, 256>>>(qkv_w, proj_w, q_bias, v_bias);
    cpb_kernel<<<1, 256>>>(cpb_w1, cpb_b1, cpb_w2);
    gemm_kernel<<<NTOK / 128, 256, GEMM_SMEM>>>(x, nullptr, nullptr, 0);        // qkv
    attn_kernel<<<NWIN, 512, ATTN_SMEM>>>(scale);                               // attention
    gemm_kernel<<<NTOK / 128, 256, GEMM_SMEM>>>(nullptr, out, proj_b, 1);       // proj
}

// round 4
// speedup vs baseline: 1.8875x; 1.0607x over previous
#include <cuda_runtime.h>
#include <cuda_bf16.h>
#include <math.h>
#include <stdint.h>

// ================= problem constants =================
#define IMG    256
#define CCH    192
#define NHEADS 6
#define DTOT   576
#define TOK    64
#define NWIN   4096
#define NTOK   262144

// ================= device scratch =================
__device__ float g_ao [(size_t)NTOK * CCH];             // 201 MB
__device__ uint32_t g_wq2[6 * 2 * 12 * 12 * 64];        // qkv frags [head][half][nt12][s12][64]
__device__ uint32_t g_wp_frag[24 * 24 * 64];            // proj frags [nt24][step24][64]
__device__ float g_bq[DTOT];
__device__ float g_rb[NHEADS * TOK * TOK];

// ================= asm helpers (baseline sm_103 PTX only) =================
__device__ __forceinline__ uint32_t smem_u32(const void* p) {
    uint32_t a;
    asm("{ .reg .u64 t; cvta.to.shared.u64 t, %1; cvt.u32.u64 %0, t; }" : "=r"(a) : "l"(p));
    return a;
}
__device__ __forceinline__ void ldsm4(uint32_t* r, uint32_t addr) {
    asm volatile("ldmatrix.sync.aligned.m8n8.x4.shared.b16 {%0,%1,%2,%3}, [%4];"
                 : "=r"(r[0]), "=r"(r[1]), "=r"(r[2]), "=r"(r[3]) : "r"(addr));
}
__device__ __forceinline__ void lds64(uint32_t* r, uint32_t addr) {
    asm volatile("ld.shared.v2.u32 {%0,%1}, [%2];" : "=r"(r[0]), "=r"(r[1]) : "r"(addr));
}
__device__ __forceinline__ void mma16816(float* d, const uint32_t* a, const uint32_t* b) {
    asm volatile("mma.sync.aligned.m16n8k16.row.col.f32.bf16.bf16.f32 "
                 "{%0,%1,%2,%3}, {%4,%5,%6,%7}, {%8,%9}, {%0,%1,%2,%3};"
                 : "+f"(d[0]), "+f"(d[1]), "+f"(d[2]), "+f"(d[3])
                 : "r"(a[0]), "r"(a[1]), "r"(a[2]), "r"(a[3]), "r"(b[0]), "r"(b[1]));
}
__device__ __forceinline__ void cpasync16(uint32_t saddr, const void* g) {
    asm volatile("cp.async.cg.shared.global [%0], [%1], 16;" :: "r"(saddr), "l"(g) : "memory");
}
#define CP_COMMIT() asm volatile("cp.async.commit_group;" ::: "memory")
#define CP_WAIT0()  asm volatile("cp.async.wait_group 0;" ::: "memory")
#define CP_WAIT1()  asm volatile("cp.async.wait_group 1;" ::: "memory")

__device__ __forceinline__ uint16_t bf_hi(float v) {
    return __bfloat16_as_ushort(__float2bfloat16(v));
}
__device__ __forceinline__ uint16_t bf_lo(float v) {
    __nv_bfloat16 h = __float2bfloat16(v);
    return __bfloat16_as_ushort(__float2bfloat16(v - __bfloat162float(h)));
}

// ================= kernel: weight prep =================
__global__ void prep_kernel(const float* __restrict__ qkv_w, const float* __restrict__ proj_w,
                            const float* __restrict__ q_bias, const float* __restrict__ v_bias) {
    int gtid = blockIdx.x * blockDim.x + threadIdx.x;
    int nth = gridDim.x * blockDim.x;
    // qkv frags: [head][half][nt 12][s 12][lane 32][2]; s<6 hi (k-step s), s>=6 lo (k-step s-6)
    for (int idx = gtid; idx < 6 * 2 * 12 * 12 * 64; idx += nth) {
        int r = idx & 1, l = (idx >> 1) & 31;
        int blk = idx >> 6;
        int s = blk % 12; blk /= 12;
        int nt = blk % 12; blk /= 12;
        int hf = blk & 1, hd = blk >> 1;
        int k = hf * 96 + (s % 6) * 16 + 2 * (l & 3) + 8 * r;
        int n = hd * 96 + nt * 8 + (l >> 2);
        float v0 = qkv_w[k * DTOT + n];
        float v1 = qkv_w[(k + 1) * DTOT + n];
        uint32_t p0 = (s < 6) ? bf_hi(v0) : bf_lo(v0);
        uint32_t p1 = (s < 6) ? bf_hi(v1) : bf_lo(v1);
        g_wq2[idx] = p0 | (p1 << 16);
    }
    // proj frags (round-3 layout): [nt 24][step 24][lane 32][2]; step<12 hi, >=12 lo
    for (int idx = gtid; idx < 24 * 24 * 64; idx += nth) {
        int r = idx & 1, l = (idx >> 1) & 31;
        int st = (idx >> 6) % 24, nt = (idx >> 6) / 24;
        int ko = 16 * (st % 12) + 2 * (l & 3) + 8 * r;
        int n = nt * 8 + (l >> 2);
        float v0 = proj_w[ko * CCH + n];
        float v1 = proj_w[(ko + 1) * CCH + n];
        uint32_t p0 = (st < 12) ? bf_hi(v0) : bf_lo(v0);
        uint32_t p1 = (st < 12) ? bf_hi(v1) : bf_lo(v1);
        g_wp_frag[idx] = p0 | (p1 << 16);
    }
    for (int n = gtid; n < DTOT; n += nth)
        g_bq[n] = (n < 192) ? q_bias[n] : ((n < 384) ? 0.0f : v_bias[n - 384]);
}

// ================= kernel: CPB MLP + gather =================
__global__ void cpb_kernel(const float* __restrict__ w1, const float* __restrict__ b1,
                           const float* __restrict__ w2) {
    __shared__ float tab16[225][6];
    int t = threadIdx.x;
    if (t < 225) {
        float ci = (float)(t / 15 - 7) * (8.0f / 7.0f);
        float cj = (float)(t % 15 - 7) * (8.0f / 7.0f);
        const float inv_log8 = 1.0f / logf(8.0f);
        float tx = copysignf(log1pf(fabsf(ci)) * inv_log8, ci);
        float ty = copysignf(log1pf(fabsf(cj)) * inv_log8, cj);
        float o[6] = {0.f, 0.f, 0.f, 0.f, 0.f, 0.f};
        for (int k = 0; k < 512; k++) {
            float h = fmaxf(tx * w1[k] + ty * w1[512 + k] + b1[k], 0.0f);
            #pragma unroll
            for (int hh = 0; hh < 6; hh++) o[hh] += h * w2[k * 6 + hh];
        }
        #pragma unroll
        for (int hh = 0; hh < 6; hh++) tab16[t][hh] = 16.0f / (1.0f + expf(-o[hh]));
    }
    __syncthreads();
    for (int idx = t; idx < NHEADS * TOK * TOK; idx += blockDim.x) {
        int h = idx >> 12;
        int r = idx & 4095;
        int p = r >> 6, q = r & 63;
        int ri = (p >> 3) - (q >> 3) + 7;
        int rj = (p & 7) - (q & 7) + 7;
        g_rb[idx] = tab16[ri * 15 + rj][h];
    }
}

// ================= fused kernel: qkv GEMM + attention (CTA = 2 windows) =================
#define A_ROW_B  784
#define OFF_A    0
#define OFF_B    100352
#define HALF_B   36864
#define OFF_Q    174080
#define QKV_LD   34
#define S_LD     68
#define FUSED_SMEM 226304   // 100352 + 73728 + 52224
#define HALF_U32 9216       // 12*12*64

__global__ __launch_bounds__(512, 1)
void fused_kernel(const float* __restrict__ x, const float* __restrict__ scale) {
    extern __shared__ char smc[];
    const uint32_t smb = smem_u32(smc);
    float* QKV = reinterpret_cast<float*>(smc + OFF_Q);   // [win2][part3][64][QKV_LD]
    float* S   = reinterpret_cast<float*>(smc + OFF_B + HALF_B);

    const int tid = threadIdx.x;
    const int wp = blockIdx.x;
    const int w = tid >> 5, lane = tid & 31;
    const int wm = w >> 2, wn = w & 3;

    // prefetch head 0 half 0
    {
        const char* gb = (const char*)g_wq2;
        #pragma unroll
        for (int i = 0; i < 5; i++) {
            int off = (tid + i * 512) * 16;
            if (off < HALF_B) cpasync16(smb + OFF_B + off, gb + off);
        }
        CP_COMMIT();
    }

    // ---- build A hi/lo from x (windowed gather) ----
    for (int idx = tid; idx < 128 * 48; idx += 512) {
        int r = idx / 48, k = (idx - r * 48) * 4;
        int wloc = r >> 6, t = r & 63;
        int win = 2 * wp + wloc;
        int b = win >> 10, wy = (win >> 5) & 31, wx = win & 31;
        int y = (wy << 3) + (t >> 3), xx = (wx << 3) + (t & 7);
        size_t tok = ((size_t)((b << 8) + y)) * IMG + xx;
        float4 v = *reinterpret_cast<const float4*>(&x[tok * CCH + k]);
        uint32_t h01 = (uint32_t)bf_hi(v.x) | ((uint32_t)bf_hi(v.y) << 16);
        uint32_t h23 = (uint32_t)bf_hi(v.z) | ((uint32_t)bf_hi(v.w) << 16);
        uint32_t l01 = (uint32_t)bf_lo(v.x) | ((uint32_t)bf_lo(v.y) << 16);
        uint32_t l23 = (uint32_t)bf_lo(v.z) | ((uint32_t)bf_lo(v.w) << 16);
        char* rowp = smc + OFF_A + r * A_ROW_B;
        *reinterpret_cast<uint2*>(rowp + 2 * k)       = make_uint2(h01, h23);
        *reinterpret_cast<uint2*>(rowp + 384 + 2 * k) = make_uint2(l01, l23);
    }

    const uint32_t a_base = smb + OFF_A + (wm * 32 + (lane & 15)) * A_ROW_B + (lane >> 4) * 16;

    for (int h = 0; h < 6; h++) {
        // issue half 1 of this head
        {
            const char* gb = (const char*)(g_wq2 + (size_t)(h * 2 + 1) * HALF_U32);
            #pragma unroll
            for (int i = 0; i < 5; i++) {
                int off = (tid + i * 512) * 16;
                if (off < HALF_B) cpasync16(smb + OFF_B + HALF_B + off, gb + off);
            }
            CP_COMMIT();
        }
        CP_WAIT1();          // half 0 ready
        __syncthreads();

        float acc[2][3][4];
        #pragma unroll
        for (int a = 0; a < 2; a++)
            #pragma unroll
            for (int bq = 0; bq < 3; bq++)
                #pragma unroll
                for (int e = 0; e < 4; e++) acc[a][bq][e] = 0.f;

        #pragma unroll
        for (int hf = 0; hf < 2; hf++) {
            if (hf == 1) { CP_WAIT0(); __syncthreads(); }
            const uint32_t bb = smb + OFF_B + hf * HALF_B;
            #pragma unroll 2
            for (int t = 0; t < 6; t++) {
                int tg = hf * 6 + t;
                uint32_t ah[2][4], al[2][4], bh[3][2], bl[3][2];
                #pragma unroll
                for (int mf = 0; mf < 2; mf++) {
                    uint32_t aaddr = a_base + mf * 16 * A_ROW_B + tg * 32;
                    ldsm4(ah[mf], aaddr);
                    ldsm4(al[mf], aaddr + 384);
                }
                #pragma unroll
                for (int nf = 0; nf < 3; nf++) {
                    int nt = wn * 3 + nf;
                    uint32_t baddr = bb + (nt * 12 + t) * 256 + lane * 8;
                    lds64(bh[nf], baddr);
                    lds64(bl[nf], baddr + 1536);   // s + 6 (lo)
                }
                #pragma unroll
                for (int mf = 0; mf < 2; mf++)
                    #pragma unroll
                    for (int nf = 0; nf < 3; nf++) {
                        mma16816(acc[mf][nf], ah[mf], bh[nf]);
                        mma16816(acc[mf][nf], al[mf], bh[nf]);
                        mma16816(acc[mf][nf], ah[mf], bl[nf]);
                    }
            }
        }

        // ---- epilogue: fragments -> smem qkv with bias ----
        #pragma unroll
        for (int mf = 0; mf < 2; mf++) {
            int rowl = wm * 32 + mf * 16 + (lane >> 2);
            int wl = rowl >> 6, rr = rowl & 63;
            #pragma unroll
            for (int nf = 0; nf < 3; nf++) {
                int col = wn * 24 + nf * 8 + 2 * (lane & 3);
                float b0 = g_bq[h * 96 + col], b1 = g_bq[h * 96 + col + 1];
                int part = col >> 5, d = col & 31;
                float* p0 = &QKV[((wl * 3 + part) * 64 + rr) * QKV_LD + d];
                p0[0] = acc[mf][nf][0] + b0;
                p0[1] = acc[mf][nf][1] + b1;
                float* p1 = &QKV[((wl * 3 + part) * 64 + rr + 8) * QKV_LD + d];
                p1[0] = acc[mf][nf][2] + b0;
                p1[1] = acc[mf][nf][3] + b1;
            }
        }
        __syncthreads();

        // ---- L2 normalize q (with logit scale) and k; 256 active ----
        if (tid < 256) {
            int wl = tid >> 7, which = (tid >> 6) & 1, row = tid & 63;
            float* rp = &QKV[((wl * 3 + which) * 64 + row) * QKV_LD];
            float ss = 0.f;
            #pragma unroll
            for (int d = 0; d < 32; d++) ss = fmaf(rp[d], rp[d], ss);
            float inv = rsqrtf(fmaxf(ss, 1.55e-05f));
            if (which == 0) {
                float sc = scale[h];
                inv *= expf(fminf(sc, 4.605170185988092f));
            }
            #pragma unroll
            for (int d = 0; d < 32; d++) rp[d] *= inv;
        }
        __syncthreads();

        // prefetch next head's half 0 (B half-0 region is free now)
        if (h < 5) {
            const char* gb = (const char*)(g_wq2 + (size_t)((h + 1) * 2) * HALF_U32);
            #pragma unroll
            for (int i = 0; i < 5; i++) {
                int off = (tid + i * 512) * 16;
                if (off < HALF_B) cpasync16(smb + OFF_B + off, gb + off);
            }
            CP_COMMIT();
        }

        // ---- attention per window ----
        for (int wl = 0; wl < 2; wl++) {
            // scores + softmax: thread = (i, jg) with 8 keys
            {
                int i = tid >> 3, jg = tid & 7;
                const float* qp = &QKV[((wl * 3 + 0) * 64 + i) * QKV_LD];
                float q[32];
                #pragma unroll
                for (int d = 0; d < 32; d += 2) {
                    float2 v2 = *reinterpret_cast<const float2*>(qp + d);
                    q[d] = v2.x; q[d + 1] = v2.y;
                }
                float p[8];
                float m = -1e30f;
                const float* rbp = &g_rb[h * 4096 + i * 64 + jg * 8];
                #pragma unroll
                for (int jj = 0; jj < 8; jj++) {
                    int j = jg * 8 + jj;
                    const float* kp = &QKV[((wl * 3 + 1) * 64 + j) * QKV_LD];
                    float dot = 0.f;
                    #pragma unroll
                    for (int d = 0; d < 32; d += 2) {
                        float2 v2 = *reinterpret_cast<const float2*>(kp + d);
                        dot = fmaf(q[d], v2.x, dot);
                        dot = fmaf(q[d + 1], v2.y, dot);
                    }
                    dot += rbp[jj];
                    p[jj] = dot;
                    m = fmaxf(m, dot);
                }
                m = fmaxf(m, __shfl_xor_sync(0xffffffffu, m, 1));
                m = fmaxf(m, __shfl_xor_sync(0xffffffffu, m, 2));
                m = fmaxf(m, __shfl_xor_sync(0xffffffffu, m, 4));
                float sum = 0.f;
                #pragma unroll
                for (int jj = 0; jj < 8; jj++) { p[jj] = __expf(p[jj] - m); sum += p[jj]; }
                sum += __shfl_xor_sync(0xffffffffu, sum, 1);
                sum += __shfl_xor_sync(0xffffffffu, sum, 2);
                sum += __shfl_xor_sync(0xffffffffu, sum, 4);
                float rinv = 1.0f / sum;
                #pragma unroll
                for (int jj = 0; jj < 8; jj++)
                    S[i * S_LD + jg * 8 + jj] = p[jj] * rinv;
            }
            __syncthreads();
            // PV: thread = (i, dg) with 4 channels
            {
                int i = tid >> 3, dg = tid & 7;
                float o[4] = {0.f, 0.f, 0.f, 0.f};
                const float* srow = &S[i * S_LD];
                #pragma unroll 4
                for (int j = 0; j < 64; j++) {
                    float pv = srow[j];
                    const float* vp = &QKV[((wl * 3 + 2) * 64 + j) * QKV_LD + dg * 4];
                    float2 v0 = *reinterpret_cast<const float2*>(vp);
                    float2 v1 = *reinterpret_cast<const float2*>(vp + 2);
                    o[0] = fmaf(pv, v0.x, o[0]);
                    o[1] = fmaf(pv, v0.y, o[1]);
                    o[2] = fmaf(pv, v1.x, o[2]);
                    o[3] = fmaf(pv, v1.y, o[3]);
                }
                int win = 2 * wp + wl;
                int b = win >> 10, wy = (win >> 5) & 31, wx = win & 31;
                int y = (wy << 3) + (i >> 3), xx = (wx << 3) + (i & 7);
                size_t tok = ((size_t)((b << 8) + y)) * IMG + xx;
                float4 st = make_float4(o[0], o[1], o[2], o[3]);
                *reinterpret_cast<float4*>(&g_ao[tok * CCH + h * 32 + dg * 4]) = st;
            }
            __syncthreads();
        }
    }
}

// ================= proj GEMM (round-3 proven) =================
#define P_A_ROW_B 784
#define P_OFF_A   0
#define P_OFF_B0  100352
#define P_OFF_B1  149504
#define PROJ_SMEM 198656
#define P_B_CHUNK 12288

__global__ __launch_bounds__(256, 1)
void proj_kernel(float* __restrict__ dst, const float* __restrict__ bias) {
    extern __shared__ char smc[];
    const uint32_t smb = smem_u32(smc);
    const int Ntot = CCH;
    const int nch = 3;

    const int tid = threadIdx.x;
    const int m0 = blockIdx.x * 128;
    const int w = tid >> 5, lane = tid & 31;
    const int wm = w >> 1, wn = w & 1;

    for (int idx = tid; idx < 128 * 48; idx += 256) {
        int r = idx / 48, k = (idx - r * 48) * 4;
        float4 v = *reinterpret_cast<const float4*>(&g_ao[(size_t)(m0 + r) * CCH + k]);
        uint32_t h01 = (uint32_t)bf_hi(v.x) | ((uint32_t)bf_hi(v.y) << 16);
        uint32_t h23 = (uint32_t)bf_hi(v.z) | ((uint32_t)bf_hi(v.w) << 16);
        uint32_t l01 = (uint32_t)bf_lo(v.x) | ((uint32_t)bf_lo(v.y) << 16);
        uint32_t l23 = (uint32_t)bf_lo(v.z) | ((uint32_t)bf_lo(v.w) << 16);
        char* rowp = smc + P_OFF_A + r * P_A_ROW_B;
        *reinterpret_cast<uint2*>(rowp + 2 * k)       = make_uint2(h01, h23);
        *reinterpret_cast<uint2*>(rowp + 384 + 2 * k) = make_uint2(l01, l23);
    }

    {
        const char* gb = (const char*)(g_wp_frag);
        #pragma unroll
        for (int i = 0; i < 12; i++) {
            int off = (tid + i * 256) * 16;
            cpasync16(smb + P_OFF_B0 + off, gb + off);
        }
        CP_COMMIT();
    }

    const uint32_t a_base = smb + P_OFF_A + (wm * 32 + (lane & 15)) * P_A_ROW_B + (lane >> 4) * 16;

    for (int c = 0; c < nch; c++) {
        if (c + 1 < nch) {
            const char* gb = (const char*)(g_wp_frag + (size_t)(c + 1) * P_B_CHUNK);
            uint32_t bb = smb + (((c + 1) & 1) ? P_OFF_B1 : P_OFF_B0);
            #pragma unroll
            for (int i = 0; i < 12; i++) {
                int off = (tid + i * 256) * 16;
                cpasync16(bb + off, gb + off);
            }
            CP_COMMIT();
            CP_WAIT1();
        } else {
            CP_WAIT0();
        }
        __syncthreads();

        const uint32_t b_base = smb + ((c & 1) ? P_OFF_B1 : P_OFF_B0);

        float acc[2][4][4];
        #pragma unroll
        for (int i = 0; i < 2; i++)
            #pragma unroll
            for (int j = 0; j < 4; j++)
                #pragma unroll
                for (int e = 0; e < 4; e++) acc[i][j][e] = 0.f;

        #pragma unroll 4
        for (int t = 0; t < 12; t++) {
            uint32_t ah[2][4], al[2][4], bh[4][2], bl[4][2];
            #pragma unroll
            for (int mf = 0; mf < 2; mf++) {
                uint32_t aaddr = a_base + mf * 16 * P_A_ROW_B + t * 32;
                ldsm4(ah[mf], aaddr);
                ldsm4(al[mf], aaddr + 384);
            }
            #pragma unroll
            for (int nf = 0; nf < 4; nf++) {
                int nt = wn * 4 + nf;
                uint32_t baddr = b_base + (((nt * 24 + t) * 32 + lane) << 3);
                lds64(bh[nf], baddr);
                lds64(bl[nf], baddr + 3072);
            }
            #pragma unroll
            for (int mf = 0; mf < 2; mf++)
                #pragma unroll
                for (int nf = 0; nf < 4; nf++) {
                    mma16816(acc[mf][nf], ah[mf], bh[nf]);
                    mma16816(acc[mf][nf], al[mf], bh[nf]);
                    mma16816(acc[mf][nf], ah[mf], bl[nf]);
                }
        }

        #pragma unroll
        for (int mf = 0; mf < 2; mf++) {
            int row = m0 + wm * 32 + mf * 16 + (lane >> 2);
            #pragma unroll
            for (int nf = 0; nf < 4; nf++) {
                int colg = c * 64 + wn * 32 + nf * 8 + 2 * (lane & 3);
                float2 bv = *reinterpret_cast<const float2*>(&bias[colg]);
                float2 v0 = make_float2(acc[mf][nf][0] + bv.x, acc[mf][nf][1] + bv.y);
                float2 v1 = make_float2(acc[mf][nf][2] + bv.x, acc[mf][nf][3] + bv.y);
                *reinterpret_cast<float2*>(&dst[(size_t)row * Ntot + colg]) = v0;
                *reinterpret_cast<float2*>(&dst[(size_t)(row + 8) * Ntot + colg]) = v1;
            }
        }
        __syncthreads();
    }
}

// ================= launch =================
extern "C" void kernel_launch(void* const* d_in, const int* in_sizes, int n_in,
                              void* d_out, int out_size) {
    (void)in_sizes; (void)n_in; (void)out_size;
    const float* x      = (const float*)d_in[0];
    const float* qkv_w  = (const float*)d_in[1];
    const float* q_bias = (const float*)d_in[2];
    const float* v_bias = (const float*)d_in[3];
    const float* scale  = (const float*)d_in[4];
    const float* cpb_w1 = (const float*)d_in[5];
    const float* cpb_b1 = (const float*)d_in[6];
    const float* cpb_w2 = (const float*)d_in[7];
    const float* proj_w = (const float*)d_in[8];
    const float* proj_b = (const float*)d_in[9];
    float* out = (float*)d_out;

    cudaFuncSetAttribute(fused_kernel, cudaFuncAttributeMaxDynamicSharedMemorySize, FUSED_SMEM);
    cudaFuncSetAttribute(proj_kernel,  cudaFuncAttributeMaxDynamicSharedMemorySize, PROJ_SMEM);

    prep_kernel<<<64, 256>>>(qkv_w, proj_w, q_bias, v_bias);
    cpb_kernel<<<1, 256>>>(cpb_w1, cpb_b1, cpb_w2);
    fused_kernel<<<NWIN / 2, 512, FUSED_SMEM>>>(x, scale);
    proj_kernel<<<NTOK / 128, 256, PROJ_SMEM>>>(out, proj_b);
}

// round 5
// speedup vs baseline: 4.1417x; 2.1943x over previous
#include <cuda_runtime.h>
#include <cuda_bf16.h>
#include <math.h>
#include <stdint.h>

// ================= problem constants =================
#define IMG    256
#define CCH    192
#define NHEADS 6
#define DTOT   576
#define TOK    64
#define NWIN   4096
#define NTOK   262144

// ================= device scratch =================
__device__ float g_ao [(size_t)NTOK * CCH];             // 201 MB
__device__ uint32_t g_wq2[6 * 2 * 12 * 12 * 64];        // qkv frags [head][half][nt12][s12][64]
__device__ uint32_t g_wp_frag[24 * 24 * 64];            // proj frags [nt24][step24][64]
__device__ float g_bq[DTOT];
__device__ float g_rb[NHEADS * TOK * TOK];

// ================= asm helpers (baseline sm_103 PTX only) =================
__device__ __forceinline__ uint32_t smem_u32(const void* p) {
    uint32_t a;
    asm("{ .reg .u64 t; cvta.to.shared.u64 t, %1; cvt.u32.u64 %0, t; }" : "=r"(a) : "l"(p));
    return a;
}
__device__ __forceinline__ void ldsm4(uint32_t* r, uint32_t addr) {
    asm volatile("ldmatrix.sync.aligned.m8n8.x4.shared.b16 {%0,%1,%2,%3}, [%4];"
                 : "=r"(r[0]), "=r"(r[1]), "=r"(r[2]), "=r"(r[3]) : "r"(addr));
}
__device__ __forceinline__ void lds64(uint32_t* r, uint32_t addr) {
    asm volatile("ld.shared.v2.u32 {%0,%1}, [%2];" : "=r"(r[0]), "=r"(r[1]) : "r"(addr));
}
__device__ __forceinline__ void mma16816(float* d, const uint32_t* a, const uint32_t* b) {
    asm volatile("mma.sync.aligned.m16n8k16.row.col.f32.bf16.bf16.f32 "
                 "{%0,%1,%2,%3}, {%4,%5,%6,%7}, {%8,%9}, {%0,%1,%2,%3};"
                 : "+f"(d[0]), "+f"(d[1]), "+f"(d[2]), "+f"(d[3])
                 : "r"(a[0]), "r"(a[1]), "r"(a[2]), "r"(a[3]), "r"(b[0]), "r"(b[1]));
}
__device__ __forceinline__ void cpasync16(uint32_t saddr, const void* g) {
    asm volatile("cp.async.cg.shared.global [%0], [%1], 16;" :: "r"(saddr), "l"(g) : "memory");
}
#define CP_COMMIT() asm volatile("cp.async.commit_group;" ::: "memory")
#define CP_WAIT0()  asm volatile("cp.async.wait_group 0;" ::: "memory")
#define CP_WAIT1()  asm volatile("cp.async.wait_group 1;" ::: "memory")

__device__ __forceinline__ uint16_t bf_hi(float v) {
    return __bfloat16_as_ushort(__float2bfloat16(v));
}
__device__ __forceinline__ uint16_t bf_lo(float v) {
    __nv_bfloat16 h = __float2bfloat16(v);
    return __bfloat16_as_ushort(__float2bfloat16(v - __bfloat162float(h)));
}
__device__ __forceinline__ uint32_t pk(uint16_t a, uint16_t b) {
    return (uint32_t)a | ((uint32_t)b << 16);
}

// ================= kernel: weight prep =================
__global__ void prep_kernel(const float* __restrict__ qkv_w, const float* __restrict__ proj_w,
                            const float* __restrict__ q_bias, const float* __restrict__ v_bias) {
    int gtid = blockIdx.x * blockDim.x + threadIdx.x;
    int nth = gridDim.x * blockDim.x;
    for (int idx = gtid; idx < 6 * 2 * 12 * 12 * 64; idx += nth) {
        int r = idx & 1, l = (idx >> 1) & 31;
        int blk = idx >> 6;
        int s = blk % 12; blk /= 12;
        int nt = blk % 12; blk /= 12;
        int hf = blk & 1, hd = blk >> 1;
        int k = hf * 96 + (s % 6) * 16 + 2 * (l & 3) + 8 * r;
        int n = hd * 96 + nt * 8 + (l >> 2);
        float v0 = qkv_w[k * DTOT + n];
        float v1 = qkv_w[(k + 1) * DTOT + n];
        uint32_t p0 = (s < 6) ? bf_hi(v0) : bf_lo(v0);
        uint32_t p1 = (s < 6) ? bf_hi(v1) : bf_lo(v1);
        g_wq2[idx] = p0 | (p1 << 16);
    }
    for (int idx = gtid; idx < 24 * 24 * 64; idx += nth) {
        int r = idx & 1, l = (idx >> 1) & 31;
        int st = (idx >> 6) % 24, nt = (idx >> 6) / 24;
        int ko = 16 * (st % 12) + 2 * (l & 3) + 8 * r;
        int n = nt * 8 + (l >> 2);
        float v0 = proj_w[ko * CCH + n];
        float v1 = proj_w[(ko + 1) * CCH + n];
        uint32_t p0 = (st < 12) ? bf_hi(v0) : bf_lo(v0);
        uint32_t p1 = (st < 12) ? bf_hi(v1) : bf_lo(v1);
        g_wp_frag[idx] = p0 | (p1 << 16);
    }
    for (int n = gtid; n < DTOT; n += nth)
        g_bq[n] = (n < 192) ? q_bias[n] : ((n < 384) ? 0.0f : v_bias[n - 384]);
}

// ================= kernel: CPB MLP + gather =================
__global__ void cpb_kernel(const float* __restrict__ w1, const float* __restrict__ b1,
                           const float* __restrict__ w2) {
    __shared__ float tab16[225][6];
    int t = threadIdx.x;
    if (t < 225) {
        float ci = (float)(t / 15 - 7) * (8.0f / 7.0f);
        float cj = (float)(t % 15 - 7) * (8.0f / 7.0f);
        const float inv_log8 = 1.0f / logf(8.0f);
        float tx = copysignf(log1pf(fabsf(ci)) * inv_log8, ci);
        float ty = copysignf(log1pf(fabsf(cj)) * inv_log8, cj);
        float o[6] = {0.f, 0.f, 0.f, 0.f, 0.f, 0.f};
        for (int k = 0; k < 512; k++) {
            float h = fmaxf(tx * w1[k] + ty * w1[512 + k] + b1[k], 0.0f);
            #pragma unroll
            for (int hh = 0; hh < 6; hh++) o[hh] += h * w2[k * 6 + hh];
        }
        #pragma unroll
        for (int hh = 0; hh < 6; hh++) tab16[t][hh] = 16.0f / (1.0f + expf(-o[hh]));
    }
    __syncthreads();
    for (int idx = t; idx < NHEADS * TOK * TOK; idx += blockDim.x) {
        int h = idx >> 12;
        int r = idx & 4095;
        int p = r >> 6, q = r & 63;
        int ri = (p >> 3) - (q >> 3) + 7;
        int rj = (p & 7) - (q & 7) + 7;
        g_rb[idx] = tab16[ri * 15 + rj][h];
    }
}

// ================= fused kernel: qkv GEMM + tensor-core attention (CTA = 2 windows) =================
#define A_ROW_B  784
#define OFF_A    0
#define OFF_B    100352
#define HALF_B   36864
#define OFF_Q    174080
#define QKV_LD   34
#define FUSED_SMEM 226304
#define HALF_U32 9216

__global__ __launch_bounds__(512, 1)
void fused_kernel(const float* __restrict__ x, const float* __restrict__ scale) {
    extern __shared__ char smc[];
    const uint32_t smb = smem_u32(smc);
    float* QKV = reinterpret_cast<float*>(smc + OFF_Q);   // [win2][part3][64][QKV_LD]

    const int tid = threadIdx.x;
    const int wp = blockIdx.x;
    const int w = tid >> 5, lane = tid & 31;
    const int wm = w >> 2, wn = w & 3;

    // prefetch head 0 half 0
    {
        const char* gb = (const char*)g_wq2;
        #pragma unroll
        for (int i = 0; i < 5; i++) {
            int off = (tid + i * 512) * 16;
            if (off < HALF_B) cpasync16(smb + OFF_B + off, gb + off);
        }
        CP_COMMIT();
    }

    // ---- build A hi/lo from x (windowed gather) ----
    for (int idx = tid; idx < 128 * 48; idx += 512) {
        int r = idx / 48, k = (idx - r * 48) * 4;
        int wloc = r >> 6, t = r & 63;
        int win = 2 * wp + wloc;
        int b = win >> 10, wy = (win >> 5) & 31, wx = win & 31;
        int y = (wy << 3) + (t >> 3), xx = (wx << 3) + (t & 7);
        size_t tok = ((size_t)((b << 8) + y)) * IMG + xx;
        float4 v = *reinterpret_cast<const float4*>(&x[tok * CCH + k]);
        uint32_t h01 = pk(bf_hi(v.x), bf_hi(v.y));
        uint32_t h23 = pk(bf_hi(v.z), bf_hi(v.w));
        uint32_t l01 = pk(bf_lo(v.x), bf_lo(v.y));
        uint32_t l23 = pk(bf_lo(v.z), bf_lo(v.w));
        char* rowp = smc + OFF_A + r * A_ROW_B;
        *reinterpret_cast<uint2*>(rowp + 2 * k)       = make_uint2(h01, h23);
        *reinterpret_cast<uint2*>(rowp + 384 + 2 * k) = make_uint2(l01, l23);
    }

    const uint32_t a_base = smb + OFF_A + (wm * 32 + (lane & 15)) * A_ROW_B + (lane >> 4) * 16;

    for (int h = 0; h < 6; h++) {
        // issue half 1 of this head
        {
            const char* gb = (const char*)(g_wq2 + (size_t)(h * 2 + 1) * HALF_U32);
            #pragma unroll
            for (int i = 0; i < 5; i++) {
                int off = (tid + i * 512) * 16;
                if (off < HALF_B) cpasync16(smb + OFF_B + HALF_B + off, gb + off);
            }
            CP_COMMIT();
        }
        CP_WAIT1();          // half 0 ready
        __syncthreads();     // also: all warps done with prev head's attention QKV reads

        float acc[2][3][4];
        #pragma unroll
        for (int a = 0; a < 2; a++)
            #pragma unroll
            for (int bq = 0; bq < 3; bq++)
                #pragma unroll
                for (int e = 0; e < 4; e++) acc[a][bq][e] = 0.f;

        #pragma unroll
        for (int hf = 0; hf < 2; hf++) {
            if (hf == 1) { CP_WAIT0(); __syncthreads(); }
            const uint32_t bb = smb + OFF_B + hf * HALF_B;
            #pragma unroll 2
            for (int t = 0; t < 6; t++) {
                int tg = hf * 6 + t;
                uint32_t ah[2][4], al[2][4], bh[3][2], bl[3][2];
                #pragma unroll
                for (int mf = 0; mf < 2; mf++) {
                    uint32_t aaddr = a_base + mf * 16 * A_ROW_B + tg * 32;
                    ldsm4(ah[mf], aaddr);
                    ldsm4(al[mf], aaddr + 384);
                }
                #pragma unroll
                for (int nf = 0; nf < 3; nf++) {
                    int nt = wn * 3 + nf;
                    uint32_t baddr = bb + (nt * 12 + t) * 256 + lane * 8;
                    lds64(bh[nf], baddr);
                    lds64(bl[nf], baddr + 1536);
                }
                #pragma unroll
                for (int mf = 0; mf < 2; mf++)
                    #pragma unroll
                    for (int nf = 0; nf < 3; nf++) {
                        mma16816(acc[mf][nf], ah[mf], bh[nf]);
                        mma16816(acc[mf][nf], al[mf], bh[nf]);
                        mma16816(acc[mf][nf], ah[mf], bl[nf]);
                    }
            }
        }

        // ---- epilogue: fragments -> smem qkv with bias ----
        #pragma unroll
        for (int mf = 0; mf < 2; mf++) {
            int rowl = wm * 32 + mf * 16 + (lane >> 2);
            int wl = rowl >> 6, rr = rowl & 63;
            #pragma unroll
            for (int nf = 0; nf < 3; nf++) {
                int col = wn * 24 + nf * 8 + 2 * (lane & 3);
                float b0 = g_bq[h * 96 + col], b1 = g_bq[h * 96 + col + 1];
                int part = col >> 5, d = col & 31;
                float* p0 = &QKV[((wl * 3 + part) * 64 + rr) * QKV_LD + d];
                p0[0] = acc[mf][nf][0] + b0;
                p0[1] = acc[mf][nf][1] + b1;
                float* p1 = &QKV[((wl * 3 + part) * 64 + rr + 8) * QKV_LD + d];
                p1[0] = acc[mf][nf][2] + b0;
                p1[1] = acc[mf][nf][3] + b1;
            }
        }
        __syncthreads();

        // ---- L2 normalize q (with logit scale) and k; 256 active ----
        if (tid < 256) {
            int wl = tid >> 7, which = (tid >> 6) & 1, row = tid & 63;
            float* rp = &QKV[((wl * 3 + which) * 64 + row) * QKV_LD];
            float ss = 0.f;
            #pragma unroll
            for (int d = 0; d < 32; d++) ss = fmaf(rp[d], rp[d], ss);
            float inv = rsqrtf(fmaxf(ss, 1.55e-05f));
            if (which == 0) {
                float sc = scale[h];
                inv *= expf(fminf(sc, 4.605170185988092f));
            }
            #pragma unroll
            for (int d = 0; d < 32; d++) rp[d] *= inv;
        }
        __syncthreads();

        // prefetch next head's half 0 (half-0 B region is free now)
        if (h < 5) {
            const char* gb = (const char*)(g_wq2 + (size_t)((h + 1) * 2) * HALF_U32);
            #pragma unroll
            for (int i = 0; i < 5; i++) {
                int off = (tid + i * 512) * 16;
                if (off < HALF_B) cpasync16(smb + OFF_B + off, gb + off);
            }
            CP_COMMIT();
        }

        // ---- tensor-core attention: 8 task warps, each (window, 16-row tile) ----
        if (w < 8) {
            const int awin = w >> 2, mt = w & 3;
            const float* Qp = &QKV[((awin * 3 + 0) * 64) * QKV_LD];
            const float* Kp = &QKV[((awin * 3 + 1) * 64) * QKV_LD];
            const float* Vp = &QKV[((awin * 3 + 2) * 64) * QKV_LD];
            const int r0 = mt * 16 + (lane >> 2);
            const int kq = 2 * (lane & 3);

            // Q fragments (hi/lo), A-operand layout
            uint32_t qh[2][4], ql[2][4];
            #pragma unroll
            for (int ks = 0; ks < 2; ks++)
                #pragma unroll
                for (int reg = 0; reg < 4; reg++) {
                    int r = r0 + ((reg & 1) << 3);
                    int k = ks * 16 + kq + ((reg >> 1) << 3);
                    float2 v = *reinterpret_cast<const float2*>(&Qp[r * QKV_LD + k]);
                    qh[ks][reg] = pk(bf_hi(v.x), bf_hi(v.y));
                    ql[ks][reg] = pk(bf_lo(v.x), bf_lo(v.y));
                }

            // S = Q @ K^T  (3-term bf16 split)
            float sa[8][4];
            #pragma unroll
            for (int nt = 0; nt < 8; nt++)
                #pragma unroll
                for (int e = 0; e < 4; e++) sa[nt][e] = 0.f;

            #pragma unroll
            for (int ks = 0; ks < 2; ks++)
                #pragma unroll
                for (int nt = 0; nt < 8; nt++) {
                    uint32_t kh[2], kl[2];
                    #pragma unroll
                    for (int reg = 0; reg < 2; reg++) {
                        int n = nt * 8 + (lane >> 2);
                        int k = ks * 16 + kq + (reg << 3);
                        float2 v = *reinterpret_cast<const float2*>(&Kp[n * QKV_LD + k]);
                        kh[reg] = pk(bf_hi(v.x), bf_hi(v.y));
                        kl[reg] = pk(bf_lo(v.x), bf_lo(v.y));
                    }
                    mma16816(sa[nt], qh[ks], kh);
                    mma16816(sa[nt], ql[ks], kh);
                    mma16816(sa[nt], qh[ks], kl);
                }

            // + relative position bias, row max
            float m0 = -1e30f, m1 = -1e30f;
            #pragma unroll
            for (int nt = 0; nt < 8; nt++) {
                const float* rbp = &g_rb[h * 4096 + r0 * 64 + nt * 8 + kq];
                float2 b0 = *reinterpret_cast<const float2*>(rbp);
                float2 b1 = *reinterpret_cast<const float2*>(rbp + 8 * 64);
                sa[nt][0] += b0.x; sa[nt][1] += b0.y;
                sa[nt][2] += b1.x; sa[nt][3] += b1.y;
                m0 = fmaxf(m0, fmaxf(sa[nt][0], sa[nt][1]));
                m1 = fmaxf(m1, fmaxf(sa[nt][2], sa[nt][3]));
            }
            m0 = fmaxf(m0, __shfl_xor_sync(0xffffffffu, m0, 1));
            m0 = fmaxf(m0, __shfl_xor_sync(0xffffffffu, m0, 2));
            m1 = fmaxf(m1, __shfl_xor_sync(0xffffffffu, m1, 1));
            m1 = fmaxf(m1, __shfl_xor_sync(0xffffffffu, m1, 2));

            float s0 = 0.f, s1 = 0.f;
            #pragma unroll
            for (int nt = 0; nt < 8; nt++) {
                sa[nt][0] = __expf(sa[nt][0] - m0); s0 += sa[nt][0];
                sa[nt][1] = __expf(sa[nt][1] - m0); s0 += sa[nt][1];
                sa[nt][2] = __expf(sa[nt][2] - m1); s1 += sa[nt][2];
                sa[nt][3] = __expf(sa[nt][3] - m1); s1 += sa[nt][3];
            }
            s0 += __shfl_xor_sync(0xffffffffu, s0, 1);
            s0 += __shfl_xor_sync(0xffffffffu, s0, 2);
            s1 += __shfl_xor_sync(0xffffffffu, s1, 1);
            s1 += __shfl_xor_sync(0xffffffffu, s1, 2);
            float ri0 = 1.0f / s0, ri1 = 1.0f / s1;

            // O = P @ V  (P hi/lo from C-fragments, V hi/lo from smem)
            float o[4][4];
            #pragma unroll
            for (int dt = 0; dt < 4; dt++)
                #pragma unroll
                for (int e = 0; e < 4; e++) o[dt][e] = 0.f;

            #pragma unroll
            for (int kp = 0; kp < 4; kp++) {
                float p0 = sa[2 * kp][0] * ri0,     p1 = sa[2 * kp][1] * ri0;
                float p2 = sa[2 * kp][2] * ri1,     p3 = sa[2 * kp][3] * ri1;
                float p4 = sa[2 * kp + 1][0] * ri0, p5 = sa[2 * kp + 1][1] * ri0;
                float p6 = sa[2 * kp + 1][2] * ri1, p7 = sa[2 * kp + 1][3] * ri1;
                uint32_t ah[4], al[4];
                ah[0] = pk(bf_hi(p0), bf_hi(p1)); al[0] = pk(bf_lo(p0), bf_lo(p1));
                ah[1] = pk(bf_hi(p2), bf_hi(p3)); al[1] = pk(bf_lo(p2), bf_lo(p3));
                ah[2] = pk(bf_hi(p4), bf_hi(p5)); al[2] = pk(bf_lo(p4), bf_lo(p5));
                ah[3] = pk(bf_hi(p6), bf_hi(p7)); al[3] = pk(bf_lo(p6), bf_lo(p7));
                #pragma unroll
                for (int dt = 0; dt < 4; dt++) {
                    uint32_t vh[2], vl[2];
                    #pragma unroll
                    for (int reg = 0; reg < 2; reg++) {
                        int j = kp * 16 + kq + (reg << 3);
                        int d = dt * 8 + (lane >> 2);
                        float va = Vp[j * QKV_LD + d];
                        float vb = Vp[(j + 1) * QKV_LD + d];
                        vh[reg] = pk(bf_hi(va), bf_hi(vb));
                        vl[reg] = pk(bf_lo(va), bf_lo(vb));
                    }
                    mma16816(o[dt], ah, vh);
                    mma16816(o[dt], al, vh);
                    mma16816(o[dt], ah, vl);
                }
            }

            // store to g_ao
            int wing = 2 * wp + awin;
            int bb_ = wing >> 10, wy = (wing >> 5) & 31, wx = wing & 31;
            #pragma unroll
            for (int half = 0; half < 2; half++) {
                int r = r0 + half * 8;
                int y = (wy << 3) + (r >> 3), xx = (wx << 3) + (r & 7);
                size_t tok = ((size_t)((bb_ << 8) + y)) * IMG + xx;
                float* op = &g_ao[tok * CCH + h * 32];
                #pragma unroll
                for (int dt = 0; dt < 4; dt++) {
                    float2 st = half ? make_float2(o[dt][2], o[dt][3])
                                     : make_float2(o[dt][0], o[dt][1]);
                    *reinterpret_cast<float2*>(&op[dt * 8 + kq]) = st;
                }
            }
        }
        // next head's top-of-loop __syncthreads orders attention reads vs epilogue writes
    }
}

// ================= proj GEMM (round-3/4 proven) =================
#define P_A_ROW_B 784
#define P_OFF_A   0
#define P_OFF_B0  100352
#define P_OFF_B1  149504
#define PROJ_SMEM 198656
#define P_B_CHUNK 12288

__global__ __launch_bounds__(256, 1)
void proj_kernel(float* __restrict__ dst, const float* __restrict__ bias) {
    extern __shared__ char smc[];
    const uint32_t smb = smem_u32(smc);
    const int Ntot = CCH;
    const int nch = 3;

    const int tid = threadIdx.x;
    const int m0 = blockIdx.x * 128;
    const int w = tid >> 5, lane = tid & 31;
    const int wm = w >> 1, wn = w & 1;

    for (int idx = tid; idx < 128 * 48; idx += 256) {
        int r = idx / 48, k = (idx - r * 48) * 4;
        float4 v = *reinterpret_cast<const float4*>(&g_ao[(size_t)(m0 + r) * CCH + k]);
        uint32_t h01 = pk(bf_hi(v.x), bf_hi(v.y));
        uint32_t h23 = pk(bf_hi(v.z), bf_hi(v.w));
        uint32_t l01 = pk(bf_lo(v.x), bf_lo(v.y));
        uint32_t l23 = pk(bf_lo(v.z), bf_lo(v.w));
        char* rowp = smc + P_OFF_A + r * P_A_ROW_B;
        *reinterpret_cast<uint2*>(rowp + 2 * k)       = make_uint2(h01, h23);
        *reinterpret_cast<uint2*>(rowp + 384 + 2 * k) = make_uint2(l01, l23);
    }

    {
        const char* gb = (const char*)(g_wp_frag);
        #pragma unroll
        for (int i = 0; i < 12; i++) {
            int off = (tid + i * 256) * 16;
            cpasync16(smb + P_OFF_B0 + off, gb + off);
        }
        CP_COMMIT();
    }

    const uint32_t a_base = smb + P_OFF_A + (wm * 32 + (lane & 15)) * P_A_ROW_B + (lane >> 4) * 16;

    for (int c = 0; c < nch; c++) {
        if (c + 1 < nch) {
            const char* gb = (const char*)(g_wp_frag + (size_t)(c + 1) * P_B_CHUNK);
            uint32_t bb = smb + (((c + 1) & 1) ? P_OFF_B1 : P_OFF_B0);
            #pragma unroll
            for (int i = 0; i < 12; i++) {
                int off = (tid + i * 256) * 16;
                cpasync16(bb + off, gb + off);
            }
            CP_COMMIT();
            CP_WAIT1();
        } else {
            CP_WAIT0();
        }
        __syncthreads();

        const uint32_t b_base = smb + ((c & 1) ? P_OFF_B1 : P_OFF_B0);

        float acc[2][4][4];
        #pragma unroll
        for (int i = 0; i < 2; i++)
            #pragma unroll
            for (int j = 0; j < 4; j++)
                #pragma unroll
                for (int e = 0; e < 4; e++) acc[i][j][e] = 0.f;

        #pragma unroll 4
        for (int t = 0; t < 12; t++) {
            uint32_t ah[2][4], al[2][4], bh[4][2], bl[4][2];
            #pragma unroll
            for (int mf = 0; mf < 2; mf++) {
                uint32_t aaddr = a_base + mf * 16 * P_A_ROW_B + t * 32;
                ldsm4(ah[mf], aaddr);
                ldsm4(al[mf], aaddr + 384);
            }
            #pragma unroll
            for (int nf = 0; nf < 4; nf++) {
                int nt = wn * 4 + nf;
                uint32_t baddr = b_base + (((nt * 24 + t) * 32 + lane) << 3);
                lds64(bh[nf], baddr);
                lds64(bl[nf], baddr + 3072);
            }
            #pragma unroll
            for (int mf = 0; mf < 2; mf++)
                #pragma unroll
                for (int nf = 0; nf < 4; nf++) {
                    mma16816(acc[mf][nf], ah[mf], bh[nf]);
                    mma16816(acc[mf][nf], al[mf], bh[nf]);
                    mma16816(acc[mf][nf], ah[mf], bl[nf]);
                }
        }

        #pragma unroll
        for (int mf = 0; mf < 2; mf++) {
            int row = m0 + wm * 32 + mf * 16 + (lane >> 2);
            #pragma unroll
            for (int nf = 0; nf < 4; nf++) {
                int colg = c * 64 + wn * 32 + nf * 8 + 2 * (lane & 3);
                float2 bv = *reinterpret_cast<const float2*>(&bias[colg]);
                float2 v0 = make_float2(acc[mf][nf][0] + bv.x, acc[mf][nf][1] + bv.y);
                float2 v1 = make_float2(acc[mf][nf][2] + bv.x, acc[mf][nf][3] + bv.y);
                *reinterpret_cast<float2*>(&dst[(size_t)row * Ntot + colg]) = v0;
                *reinterpret_cast<float2*>(&dst[(size_t)(row + 8) * Ntot + colg]) = v1;
            }
        }
        __syncthreads();
    }
}

// ================= launch =================
extern "C" void kernel_launch(void* const* d_in, const int* in_sizes, int n_in,
                              void* d_out, int out_size) {
    (void)in_sizes; (void)n_in; (void)out_size;
    const float* x      = (const float*)d_in[0];
    const float* qkv_w  = (const float*)d_in[1];
    const float* q_bias = (const float*)d_in[2];
    const float* v_bias = (const float*)d_in[3];
    const float* scale  = (const float*)d_in[4];
    const float* cpb_w1 = (const float*)d_in[5];
    const float* cpb_b1 = (const float*)d_in[6];
    const float* cpb_w2 = (const float*)d_in[7];
    const float* proj_w = (const float*)d_in[8];
    const float* proj_b = (const float*)d_in[9];
    float* out = (float*)d_out;

    cudaFuncSetAttribute(fused_kernel, cudaFuncAttributeMaxDynamicSharedMemorySize, FUSED_SMEM);
    cudaFuncSetAttribute(proj_kernel,  cudaFuncAttributeMaxDynamicSharedMemorySize, PROJ_SMEM);

    prep_kernel<<<64, 256>>>(qkv_w, proj_w, q_bias, v_bias);
    cpb_kernel<<<1, 256>>>(cpb_w1, cpb_b1, cpb_w2);
    fused_kernel<<<NWIN / 2, 512, FUSED_SMEM>>>(x, scale);
    proj_kernel<<<NTOK / 128, 256, PROJ_SMEM>>>(out, proj_b);
}